// round 16
// baseline (speedup 1.0000x reference)
#include <cuda_runtime.h>
#include <cuda_bf16.h>

#define BEV_H 512
#define BEV_W 512
#define BEV_C 64
#define HW (BEV_H * BEV_W)   // 262144 = 2^18

// Scratch: last-writer pillar index per BEV cell (up to 8 batches).
__device__ int g_last[8 * HW];
// Zero row for empty cells (zero-initialized, never written).
__device__ __align__(16) float g_zero[BEV_C];

// ---------------------------------------------------------------------------
// Scatter: one pillar per thread (200k threads -> latency well covered).
// ---------------------------------------------------------------------------
__global__ void __launch_bounds__(256) bev_scatter_kernel(
    const int* __restrict__ coords, int P) {
    int p = blockIdx.x * blockDim.x + threadIdx.x;
    if (p >= P) return;
    int b = __ldg(&coords[3 * p + 0]);
    int r = __ldg(&coords[3 * p + 1]);
    int c = __ldg(&coords[3 * p + 2]);
    r = min(max(r, 0), BEV_H - 1);
    c = min(max(c, 0), BEV_W - 1);
    atomicMax(&g_last[b * HW + r * BEV_W + c], p);
}

// ---------------------------------------------------------------------------
// Gather + transpose: warp-autonomous register transpose (R13/R15 structure,
// 6 wf/cell) with a register budget cap (__launch_bounds__(256,6)) to reach
// ~75% occupancy — the A/B test isolating occupancy as the lever.
// Team (q=l&3, cw=l>>2) covers cells 4cw..4cw+3; pass k: lane q loads chunk
// (q+4k) of each of its 4 rows -> holds 4 consecutive cells x 4 channels;
// stores are float4 along W gathered from components (register MOVs only).
// Passes software-pipelined (pass k+1 loads issue before pass k stores).
// ---------------------------------------------------------------------------
__device__ __forceinline__ const float4* row_ptr(const float* feats, int lc) {
    return reinterpret_cast<const float4*>(
        lc >= 0 ? feats + (size_t)lc * BEV_C : g_zero);
}

__global__ void __launch_bounds__(256, 6) bev_gather_kernel(
    const float* __restrict__ feats,
    float* __restrict__ out) {
    const int t  = blockIdx.x * 256 + threadIdx.x;
    const int w  = t >> 5;          // global warp id
    const int l  = t & 31;
    const int q  = l & 3;           // chunk lane within team
    const int cw = l >> 2;          // team id: cells 4cw..4cw+3

    const int base = w * 32;        // first cell (32-aligned, in-batch)
    const int b    = base >> 18;
    const int pos  = base & (HW - 1);

    // Coalesced g_last load; team's 4 cell indices via shuffle.
    const int myLast = __ldg(&g_last[base + l]);
    const float4* rp[4];
#pragma unroll
    for (int r = 0; r < 4; r++)
        rp[r] = row_ptr(feats, __shfl_sync(0xffffffffu, myLast, 4 * cw + r));

    // Lane's store base: cells pos+4cw.. of channel column 4q (+16k +e).
    float* outb = out + (size_t)b * (BEV_C * HW) + pos + 4 * cw
                + (size_t)(4 * q) * HW;

    // ---- pass 0 loads: chunk q of each of the 4 cell rows ----
    float4 A[4], B[4];
#pragma unroll
    for (int r = 0; r < 4; r++) A[r] = __ldg(rp[r] + q);

#pragma unroll
    for (int k = 0; k < 4; k++) {
        // prefetch pass k+1 (issues before pass k's stores consume A)
        if (k < 3) {
#pragma unroll
            for (int r = 0; r < 4; r++) B[r] = __ldg(rp[r] + q + 4 * (k + 1));
        }

        // store pass k: channels 4(q+4k)+e, e=0..3; float4 along W, evict-first
        float* oc = outb + (size_t)(16 * k) * HW;
        float4 s;
        s.x = A[0].x; s.y = A[1].x; s.z = A[2].x; s.w = A[3].x;
        __stcs(reinterpret_cast<float4*>(oc + 0 * (size_t)HW), s);
        s.x = A[0].y; s.y = A[1].y; s.z = A[2].y; s.w = A[3].y;
        __stcs(reinterpret_cast<float4*>(oc + 1 * (size_t)HW), s);
        s.x = A[0].z; s.y = A[1].z; s.z = A[2].z; s.w = A[3].z;
        __stcs(reinterpret_cast<float4*>(oc + 2 * (size_t)HW), s);
        s.x = A[0].w; s.y = A[1].w; s.z = A[2].w; s.w = A[3].w;
        __stcs(reinterpret_cast<float4*>(oc + 3 * (size_t)HW), s);

#pragma unroll
        for (int r = 0; r < 4; r++) A[r] = B[r];
    }
}

extern "C" void kernel_launch(void* const* d_in, const int* in_sizes, int n_in,
                              void* d_out, int out_size) {
    const float* feats  = (const float*)d_in[0];   // (P, 64) float32
    const int*   coords = (const int*)d_in[1];     // (P, 3) int32
    float*       out    = (float*)d_out;           // (B, 64, 512, 512) float32

    int P = in_sizes[0] / BEV_C;
    int B = out_size / (BEV_C * HW);
    if (B > 8) B = 8;
    int ncells = B * HW;

    // 1) init last-index grid to -1 (memset node; 0xFF bytes == -1 int)
    void* lastPtr = nullptr;
    cudaGetSymbolAddress(&lastPtr, g_last);
    cudaMemsetAsync(lastPtr, 0xFF, (size_t)ncells * sizeof(int), 0);

    // 2) scatter: one pillar per thread
    bev_scatter_kernel<<<(P + 255) / 256, 256>>>(coords, P);

    // 3) gather + transpose: 32 cells per warp, 8 warps per CTA
    bev_gather_kernel<<<ncells / 256, 256>>>(feats, out);
}

// round 17
// speedup vs baseline: 1.0293x; 1.0293x over previous
#include <cuda_runtime.h>
#include <cuda_bf16.h>

#define BEV_H 512
#define BEV_W 512
#define BEV_C 64
#define HW (BEV_H * BEV_W)   // 262144 = 2^18

// Scratch: last-writer pillar index per BEV cell (up to 8 batches).
__device__ int g_last[8 * HW];
// Zero row for empty cells (zero-initialized, never written).
__device__ __align__(16) float g_zero[BEV_C];

// ---------------------------------------------------------------------------
// Scatter: one pillar per thread; last-occurrence-wins via atomicMax.
// 200k threads cover the atomics' L2 latency without per-thread batching.
// ---------------------------------------------------------------------------
__global__ void __launch_bounds__(256) bev_scatter_kernel(
    const int* __restrict__ coords, int P) {
    int p = blockIdx.x * blockDim.x + threadIdx.x;
    if (p >= P) return;
    int b = __ldg(&coords[3 * p + 0]);
    int r = __ldg(&coords[3 * p + 1]);
    int c = __ldg(&coords[3 * p + 2]);
    r = min(max(r, 0), BEV_H - 1);
    c = min(max(c, 0), BEV_W - 1);
    atomicMax(&g_last[b * HW + r * BEV_W + c], p);
}

// ---------------------------------------------------------------------------
// Gather + transpose (R6, the best-measured variant: 51.9us, occ 78.5%).
// Warp-autonomous, zero smem/barriers. Each warp owns 8 consecutive cells.
// Lane (q = l&3, cw = l>>2):
//   Load:  4-lane team per cell; lane q loads float4 #q, q+4, q+8, q+12 of
//          its cell's row -> per LDG.128 the warp touches 8 rows x 64B.
//   Store: lane holds channels {16k+4q+j}; 16 STG.32, each instruction writes
//          4 channels x 8 consecutive cells = 4 aligned 32B sectors;
//          consecutive warps extend them to full 128B lines in L2.
// ---------------------------------------------------------------------------
__global__ void __launch_bounds__(256) bev_gather_kernel(
    const float* __restrict__ feats,
    float* __restrict__ out) {
    const int t  = blockIdx.x * 256 + threadIdx.x;
    const int w  = t >> 5;          // global warp id == 8-cell group id
    const int l  = t & 31;
    const int q  = l & 3;           // lane quarter within the 4-lane row team
    const int cw = l >> 2;          // 0..7: cell within group

    const int base = w * 8;                 // first cell of group (8 | HW)
    const int cell = base + cw;

    const int last = __ldg(&g_last[cell]);
    const float4* row = reinterpret_cast<const float4*>(
        last >= 0 ? feats + (size_t)last * BEV_C : g_zero);

    float4 v0 = __ldg(row + q + 0);   // channels 4q+0..3
    float4 v1 = __ldg(row + q + 4);   // channels 16+4q+0..3
    float4 v2 = __ldg(row + q + 8);   // channels 32+4q+0..3
    float4 v3 = __ldg(row + q + 12);  // channels 48+4q+0..3

    const int b   = base >> 18;       // group never crosses a batch
    const int pos = base & (HW - 1);
    float* ob = out + (size_t)b * (BEV_C * HW) + pos + cw;

    const size_t chb = (size_t)(4 * q) * HW;  // channel offset base for this lane
#pragma unroll
    for (int k = 0; k < 4; k++) {
        float4 v = (k == 0) ? v0 : (k == 1) ? v1 : (k == 2) ? v2 : v3;
        float* o = ob + (size_t)(16 * k) * HW + chb;
        o[0 * HW] = v.x;
        o[1 * HW] = v.y;
        o[2 * (size_t)HW] = v.z;
        o[3 * (size_t)HW] = v.w;
    }
}

extern "C" void kernel_launch(void* const* d_in, const int* in_sizes, int n_in,
                              void* d_out, int out_size) {
    const float* feats  = (const float*)d_in[0];   // (P, 64) float32
    const int*   coords = (const int*)d_in[1];     // (P, 3) int32
    float*       out    = (float*)d_out;           // (B, 64, 512, 512) float32

    int P = in_sizes[0] / BEV_C;
    int B = out_size / (BEV_C * HW);
    if (B > 8) B = 8;
    int ncells = B * HW;

    // 1) init last-index grid to -1 (memset node; 0xFF bytes == -1 int)
    void* lastPtr = nullptr;
    cudaGetSymbolAddress(&lastPtr, g_last);
    cudaMemsetAsync(lastPtr, 0xFF, (size_t)ncells * sizeof(int), 0);

    // 2) scatter: one pillar per thread
    bev_scatter_kernel<<<(P + 255) / 256, 256>>>(coords, P);

    // 3) gather + transpose: one warp per 8 cells, 8 warps per CTA
    int gblocks = ncells / 64;   // (ncells/8 groups) / (8 warps per CTA)
    bev_gather_kernel<<<gblocks, 256>>>(feats, out);
}